// round 13
// baseline (speedup 1.0000x reference)
#include <cuda_runtime.h>
#include <math.h>

#define Bc   16
#define Cc   3
#define Rc   512
#define Ac   512
#define Gc   4096
#define Kc   4
#define NS   41     // shifts -20..+20
#define Qc   4      // 3 channels + channel-sum

// Transposed SAT layout: value SAT[r][a] stored at slice[BOFF + a*RPT + r]
#define RPT  544
#define BOFF 31
#define SST  (513 * RPT + 64)

#define YST  513                      // smem Y stride (a-major), odd -> conflict-free
#define SMEM_BYTES ((64 * YST + 32 * 64) * 4)

// Static scratch
__device__ float g_satc[(size_t)Bc * Cc * SST];      // transposed per-channel SAT
__device__ float g_sata[(size_t)Bc * SST];           // transposed channel-sum SAT
__device__ float g_tot[(size_t)Bc * Qc * 32 * 512];  // col-scan tile totals [bq][t][r]
__device__ float g_w[NS];                            // w[s] = exp(-|s-20|/200)

// ================= fused row-scan + col-scan -> transposed SAT ==============
// Cluster of 8 CTAs per (b,q) slice. CTA c owns a-chunk [64c, 64c+64).
// Exact XLA ReduceWindowRewriter(base=16) DAG on both axes.
__global__ void __launch_bounds__(512, 1) __cluster_dims__(8, 1, 1)
k_fused(const float* __restrict__ pred)
{
    extern __shared__ float smem[];
    float* s_y  = smem;                 // [64 a][YST] row-scan inner values
    float* s_t1 = smem + 64 * YST;      // [32 t][64 a] row tile totals/carries

    const int tid = threadIdx.x;
    const int c   = blockIdx.x & 7;     // cluster rank (a-chunk)
    const int bq  = blockIdx.x >> 3;
    const int q   = bq & 3;
    const int b   = bq >> 2;

    if (blockIdx.x == 0 && tid < NS) {
        const int sh = tid - 20;
        float xw = __fdiv_rn(-(float)(sh < 0 ? -sh : sh), 200.0f);
        g_w[tid] = (float)exp((double)xw);
    }

    float* dstb = (q < 3)
        ? g_satc + (size_t)(b * Cc + q) * SST + BOFF
        : g_sata + (size_t)b * SST + BOFF;

    // fused SAT border zeros
    if (c == 0) {
        for (int i = tid; i < 513; i += 512) dstb[i] = 0.f;          // a=0 plane
    }
    if (tid < 64) dstb[(size_t)(64 * c + 1 + tid) * RPT] = 0.f;      // r=0 plane

    // ---- phase 1: row scan (along r) for 64 owned columns -------------------
    {
        const int ax = tid & 63;        // local a
        const int tg = tid >> 6;        // 0..7, tiles 4tg..4tg+3
        const int a  = 64 * c + ax;
        const float* p0 = pred + ((size_t)b * Cc * Rc) * Ac + a;

        #pragma unroll
        for (int it = 0; it < 4; it++) {
            const int t = tg * 4 + it;
            float px[16];
            if (q < 3) {
                const float* pc = p0 + ((size_t)q * Rc + (size_t)t * 16) * Ac;
                #pragma unroll
                for (int j = 0; j < 16; j++) px[j] = __ldg(pc + (size_t)j * Ac);
            } else {
                #pragma unroll
                for (int j = 0; j < 16; j++) {
                    const int r = t * 16 + j;
                    float v0 = __ldg(p0 + (size_t)r * Ac);
                    float v1 = __ldg(p0 + ((size_t)Rc + r) * Ac);
                    float v2 = __ldg(p0 + ((size_t)2 * Rc + r) * Ac);
                    px[j] = __fadd_rn(__fadd_rn(v0, v1), v2);   // (p0+p1)+p2
                }
            }
            #pragma unroll
            for (int j = 1; j < 16; j++) px[j] = __fadd_rn(px[j-1], px[j]);
            #pragma unroll
            for (int j = 0; j < 16; j++) s_y[ax * YST + t * 16 + j] = px[j];
            s_t1[t * 64 + ax] = px[15];
        }
    }
    __syncthreads();

    // row totals fold per column ax (exact low/U0/high order); carries in s_t1
    if (tid < 64) {
        const int ax = tid;
        float acc = s_t1[0 * 64 + ax];
        #pragma unroll
        for (int t2 = 1; t2 < 16; t2++) {
            float T = s_t1[t2 * 64 + ax];
            s_t1[t2 * 64 + ax] = acc;
            acc = __fadd_rn(acc, T);
        }
        float U0  = acc;
        float T16 = s_t1[16 * 64 + ax];
        s_t1[16 * 64 + ax] = acc;
        float acch = T16;
        acc = __fadd_rn(U0, acch);
        #pragma unroll
        for (int t2 = 17; t2 < 32; t2++) {
            float T = s_t1[t2 * 64 + ax];
            s_t1[t2 * 64 + ax] = acc;
            acch = __fadd_rn(acch, T);
            acc = __fadd_rn(U0, acch);
        }
    }
    __syncthreads();

    // ---- phase 2a: col-scan inner prefixes (apply row carry on the fly) -----
    {
        const int r    = tid;
        const int rowt = r >> 4;
        #pragma unroll
        for (int lt = 0; lt < 4; lt++) {
            float px[16];
            #pragma unroll
            for (int j = 0; j < 16; j++) {
                const int a_l = 16 * lt + j;
                float raw = s_y[a_l * YST + r];
                float v = (rowt == 0) ? raw : __fadd_rn(s_t1[rowt * 64 + a_l], raw);
                px[j] = (j == 0) ? v : __fadd_rn(px[j-1], v);
            }
            #pragma unroll
            for (int j = 0; j < 16; j++) s_y[(16 * lt + j) * YST + r] = px[j];
            g_tot[((size_t)bq * 32 + (4 * c + lt)) * 512 + r] = px[15];
        }
    }
    __threadfence();
    asm volatile("barrier.cluster.arrive.aligned;" ::: "memory");
    asm volatile("barrier.cluster.wait.aligned;"   ::: "memory");

    // ---- phase 2b: cross-CTA carries — INDEPENDENT loads, then exact fold ---
    {
        const int r    = tid;
        const int base = 4 * c;
        const float* Tp = g_tot + (size_t)bq * 32 * 512 + r;
        float carry4[4] = {0.f, 0.f, 0.f, 0.f};

        // independent loads: low totals T[0..15], high totals T[16..base+2]
        float Tv[16];
        #pragma unroll
        for (int t2 = 0; t2 < 16; t2++)
            Tv[t2] = __ldcg(Tp + (size_t)t2 * 512);
        float Th[15];
        if (c >= 4) {
            #pragma unroll
            for (int i = 0; i < 15; i++)
                if (16 + i <= base + 2) Th[i] = __ldcg(Tp + (size_t)(16 + i) * 512);
        }

        if (c == 0) {
            carry4[1] = Tv[0];
            carry4[2] = __fadd_rn(carry4[1], Tv[1]);
            carry4[3] = __fadd_rn(carry4[2], Tv[2]);
        } else if (c <= 3) {
            float f = Tv[0];
            #pragma unroll
            for (int t2 = 1; t2 < 12; t2++)
                if (t2 <= base - 1) f = __fadd_rn(f, Tv[t2]);
            carry4[0] = f;                               // incT[base-1]
            f = __fadd_rn(f, Tv[base]);     carry4[1] = f;
            f = __fadd_rn(f, Tv[base + 1]); carry4[2] = f;
            f = __fadd_rn(f, Tv[base + 2]); carry4[3] = f;
        } else {
            float U0 = Tv[0];
            #pragma unroll
            for (int t2 = 1; t2 < 16; t2++) U0 = __fadd_rn(U0, Tv[t2]);
            if (c == 4) {
                carry4[0] = U0;                          // carry(16) = incT[15] = U0
                float gg = Th[0];
                carry4[1] = __fadd_rn(U0, gg);
                gg = __fadd_rn(gg, Th[1]); carry4[2] = __fadd_rn(U0, gg);
                gg = __fadd_rn(gg, Th[2]); carry4[3] = __fadd_rn(U0, gg);
            } else {
                float gg = Th[0];
                #pragma unroll
                for (int t2 = 17; t2 < 28; t2++)
                    if (t2 <= base - 1) gg = __fadd_rn(gg, Th[t2 - 16]);
                carry4[0] = __fadd_rn(U0, gg);           // incT[base-1]
                gg = __fadd_rn(gg, Th[base - 16]); carry4[1] = __fadd_rn(U0, gg);
                gg = __fadd_rn(gg, Th[base - 15]); carry4[2] = __fadd_rn(U0, gg);
                gg = __fadd_rn(gg, Th[base - 14]); carry4[3] = __fadd_rn(U0, gg);
            }
        }

        #pragma unroll
        for (int lt = 0; lt < 4; lt++) {
            const int gt = base + lt;
            #pragma unroll
            for (int j = 0; j < 16; j++) {
                float v = s_y[(16 * lt + j) * YST + r];
                s_y[(16 * lt + j) * YST + r] = (gt == 0) ? v : __fadd_rn(carry4[lt], v);
            }
        }
    }
    __syncthreads();

    // ---- final coalesced transposed store: SAT_T[a+1][r+1] ------------------
    {
        const int r = tid;
        #pragma unroll 4
        for (int a_l = 0; a_l < 64; a_l++) {
            dstb[(size_t)(64 * c + a_l + 1) * RPT + (r + 1)] = s_y[a_l * YST + r];
        }
    }
}

// ---------------- K3: per-detection vals; warp-0 epilogue -------------------
__global__ void __launch_bounds__(192) k_detect(
    const int* __restrict__ det_b, const int* __restrict__ det_c,
    const int* __restrict__ det_r, const int* __restrict__ det_a,
    const int* __restrict__ radus, const float* __restrict__ pred,
    float* __restrict__ out)
{
    const int g = blockIdx.x;
    const int t = threadIdx.x;

    __shared__ float v3[Kc][NS];

    if (t < Kc * NS) {
        const int k  = t / NS;
        const int s  = t % NS;
        const int sh = s - 20;
        const int gk = g * Kc + k;
        const int dr = det_r[gk], da = det_a[gk], db = det_b[gk];
        const int dc = det_c[gk], rad = radus[gk];

        const int rc = dr + sh;
        const int r1 = min(max(rc - rad, 0), Rc);
        const int r2 = min(max(rc + rad + 1, 0), Rc);
        const int a1 = min(max(da - 2, 0), Ac);
        const int a2 = min(max(da + 3, 0), Ac);

        const float w = g_w[s];

        const float* sc = g_satc + (size_t)(db * Cc + dc) * SST + BOFF;
        const float* sa = g_sata + (size_t)db * SST + BOFF;

        float c22 = __ldg(sc + (size_t)a2 * RPT + r2), c12 = __ldg(sc + (size_t)a2 * RPT + r1);
        float c21 = __ldg(sc + (size_t)a1 * RPT + r2), c11 = __ldg(sc + (size_t)a1 * RPT + r1);
        float rect4 = __fadd_rn(__fsub_rn(__fsub_rn(c22, c12), c21), c11);
        float val1  = __fmul_rn(rect4, w);

        float d22 = __ldg(sa + (size_t)a2 * RPT + r2), d12 = __ldg(sa + (size_t)a2 * RPT + r1);
        float d21 = __ldg(sa + (size_t)a1 * RPT + r2), d11 = __ldg(sa + (size_t)a1 * RPT + r1);
        float rect3 = __fadd_rn(__fsub_rn(__fsub_rn(d22, d12), d21), d11);
        float val2  = __fmul_rn(rect3, w);

        float val3 = __fadd_rn(__fmul_rn(0.5f, val1),
                               __fmul_rn(0.5f, __fsub_rn(val2, val1)));
        v3[k][s] = val3;
    }
    __syncthreads();

    if (t < 32) {   // warp 0 epilogue
        const int s1 = t;
        float bv;
        int   bi = s1;
        float se1 = __fadd_rn(__fadd_rn(__fadd_rn(v3[0][s1], v3[1][s1]), v3[2][s1]), v3[3][s1]);
        out[(size_t)g * NS + s1] = se1;
        bv = se1;
        const int s2 = t + 32;
        if (s2 < NS) {
            float se2 = __fadd_rn(__fadd_rn(__fadd_rn(v3[0][s2], v3[1][s2]), v3[2][s2]), v3[3][s2]);
            out[(size_t)g * NS + s2] = se2;
            if (se2 > bv) { bv = se2; bi = s2; }
        }
        #pragma unroll
        for (int off = 16; off > 0; off >>= 1) {
            float ov = __shfl_xor_sync(0xffffffffu, bv, off);
            int   oi = __shfl_xor_sync(0xffffffffu, bi, off);
            if (ov > bv || (ov == bv && oi < bi)) { bv = ov; bi = oi; }
        }
        const int shift = bi - 20;

        float pmv = 0.3f;
        if (t < 12) {
            const int kk = t / 3, cch = t % 3;
            const int gg = g * Kc + kk;
            const int rr = min(max(det_r[gg] + shift, 0), Rc - 1);
            const int db = det_b[gg], da = det_a[gg];
            pmv = fmaxf(pmv, __ldg(pred + (((size_t)db * Cc + cch) * Rc + rr) * Ac + da));
        }
        #pragma unroll
        for (int off = 16; off > 0; off >>= 1)
            pmv = fmaxf(pmv, __shfl_xor_sync(0xffffffffu, pmv, off));

        if (t == 0) {
            out[(size_t)Gc * NS       + g] = (float)shift;
            out[(size_t)Gc * (NS + 1) + g] = bv;
            out[(size_t)Gc * (NS + 2) + g] = pmv;
        }
    }
}

extern "C" void kernel_launch(void* const* d_in, const int* in_sizes, int n_in,
                              void* d_out, int out_size)
{
    const float* pred  = (const float*)d_in[0];
    const int*   det_b = (const int*)  d_in[1];
    const int*   det_c = (const int*)  d_in[2];
    const int*   det_r = (const int*)  d_in[3];
    const int*   det_a = (const int*)  d_in[4];
    const int*   radus = (const int*)  d_in[5];
    float*       out   = (float*)d_out;

    (void)cudaFuncSetAttribute(k_fused,
        cudaFuncAttributeMaxDynamicSharedMemorySize, SMEM_BYTES);

    k_fused<<<Bc * Qc * 8, 512, SMEM_BYTES>>>(pred);   // 512 CTAs, clusters of 8
    k_detect<<<Gc, 192>>>(det_b, det_c, det_r, det_a, radus, pred, out);
}

// round 14
// speedup vs baseline: 1.1979x; 1.1979x over previous
#include <cuda_runtime.h>
#include <math.h>

#define Bc   16
#define Cc   3
#define Rc   512
#define Ac   512
#define Gc   4096
#define Kc   4
#define NS   41     // shifts -20..+20
#define Qc   4      // 3 channels + channel-sum

// Transposed SAT layout: value SAT[r][a] stored at slice[BOFF + a*RPT + r]
#define RPT  544
#define BOFF 31
#define SST  (513 * RPT + 64)

// Static scratch
__device__ float g_y[(size_t)Bc * Qc * Rc * Ac];    // row-cumsum
__device__ float g_satc[(size_t)Bc * Cc * SST];     // transposed per-channel SAT
__device__ float g_sata[(size_t)Bc * SST];          // transposed channel-sum SAT
__device__ float g_w[NS];                           // w[s] = exp(-|s-20|/200)

// ---- one XLA ReduceWindowRewriter(base=16) scan over 512 elems, in-block ---
__device__ __forceinline__ void scan_block(float (&px)[16], float* dst,
                                           int t, int tx, float (*s_tot)[33])
{
    #pragma unroll
    for (int j = 1; j < 16; j++) px[j] = __fadd_rn(px[j-1], px[j]);
    s_tot[t][tx] = px[15];
    __syncthreads();

    if (t == 0) {
        float acc = s_tot[0][tx];                    // incT[0]
        #pragma unroll
        for (int t2 = 1; t2 < 16; t2++) {
            float T = s_tot[t2][tx];
            s_tot[t2][tx] = acc;                     // carry[t2] = incT[t2-1]
            acc = __fadd_rn(acc, T);
        }
        float U0  = acc;                             // fold of T[0..15]
        float T16 = s_tot[16][tx];
        s_tot[16][tx] = acc;                         // carry[16] = incT[15]
        float acch = T16;
        acc = __fadd_rn(U0, acch);                   // incT[16]
        #pragma unroll
        for (int t2 = 17; t2 < 32; t2++) {
            float T = s_tot[t2][tx];
            s_tot[t2][tx] = acc;                     // carry[t2] = incT[t2-1]
            acch = __fadd_rn(acch, T);
            acc = __fadd_rn(U0, acch);
        }
    }
    __syncthreads();

    const float carry = s_tot[t][tx];
    #pragma unroll
    for (int j = 0; j < 16; j++) {
        float o = (t == 0) ? px[j] : __fadd_rn(carry, px[j]);
        dst[(size_t)j * Ac] = o;
    }
    __syncthreads();
}

// ---------------- K1: fused row-axis scans (half of b's) --------------------
__global__ void __launch_bounds__(1024) k_rowscan(const float* __restrict__ pred,
                                                  int b_base)
{
    if (b_base == 0 && blockIdx.x == 0 && threadIdx.x < NS) {
        const int sh = (int)threadIdx.x - 20;
        float xw = __fdiv_rn(-(float)(sh < 0 ? -sh : sh), 200.0f);
        g_w[threadIdx.x] = (float)exp((double)xw);
    }

    const int blk  = blockIdx.x;          // 0..127 per half
    const int acol = blk & 15;
    const int b    = b_base + (blk >> 4);
    const int tx   = threadIdx.x & 31;
    const int t    = threadIdx.x >> 5;    // tile 0..31
    const int a    = acol * 32 + tx;

    __shared__ float s_tot[32][33];

    const float* p  = pred + ((size_t)b * Cc * Rc) * Ac + a;
    float*       yb = g_y  + ((size_t)b * Qc * Rc) * Ac + a;

    float ps[16];   // running channel sum, exact (v0+v1)+v2 order

    #pragma unroll
    for (int c = 0; c < 3; c++) {
        float px[16];
        const float* pc = p + ((size_t)c * Rc + (size_t)t * 16) * Ac;
        #pragma unroll
        for (int j = 0; j < 16; j++) px[j] = __ldg(pc + (size_t)j * Ac);
        #pragma unroll
        for (int j = 0; j < 16; j++)
            ps[j] = (c == 0) ? px[j] : __fadd_rn(ps[j], px[j]);
        scan_block(px, yb + ((size_t)c * Rc + (size_t)t * 16) * Ac, t, tx, s_tot);
    }
    scan_block(ps, yb + ((size_t)3 * Rc + (size_t)t * 16) * Ac, t, tx, s_tot);
}

// ---------------- K2: col-axis scans -> TRANSPOSED SAT (half of b's) --------
__global__ void __launch_bounds__(512) k_colscan(int b_base)
{
    const int blk  = blockIdx.x;           // (b,q,rblk): 8*4*32 per half
    const int rblk = blk & 31;
    const int q    = (blk >> 5) & 3;
    const int b    = b_base + (blk >> 7);
    const int tid  = threadIdx.x;
    const int ty   = tid & 15;              // row in stripe
    const int t    = tid >> 4;              // a-tile 0..31

    __shared__ float s_in[16][545];
    __shared__ float s_tot[16][33];

    const float* src = g_y + (((size_t)b * Qc + q) * Rc + (size_t)rblk * 16) * Ac;

    #pragma unroll
    for (int i = 0; i < 16; i++) {
        int idx = i * 512 + tid;
        int rr = idx >> 9, cc = idx & 511;
        s_in[rr][cc + (cc >> 4)] = src[(size_t)rr * Ac + cc];
    }
    __syncthreads();

    float px[16];
    #pragma unroll
    for (int j = 0; j < 16; j++) px[j] = s_in[ty][17 * t + j];
    #pragma unroll
    for (int j = 1; j < 16; j++) px[j] = __fadd_rn(px[j-1], px[j]);
    s_tot[ty][t] = px[15];
    __syncthreads();

    if (t == 0) {
        float acc = s_tot[ty][0];
        #pragma unroll
        for (int t2 = 1; t2 < 16; t2++) {
            float T = s_tot[ty][t2];
            s_tot[ty][t2] = acc;
            acc = __fadd_rn(acc, T);
        }
        float U0  = acc;
        float T16 = s_tot[ty][16];
        s_tot[ty][16] = acc;
        float acch = T16;
        acc = __fadd_rn(U0, acch);
        #pragma unroll
        for (int t2 = 17; t2 < 32; t2++) {
            float T = s_tot[ty][t2];
            s_tot[ty][t2] = acc;
            acch = __fadd_rn(acch, T);
            acc = __fadd_rn(U0, acch);
        }
    }
    __syncthreads();

    const float carry = s_tot[ty][t];
    float* dstb = (q < 3)
        ? g_satc + (size_t)(b * Cc + q) * SST + BOFF
        : g_sata + (size_t)b * SST + BOFF;
    const int r = rblk * 16 + ty;

    #pragma unroll
    for (int j = 0; j < 16; j++) {
        float o = (t == 0) ? px[j] : __fadd_rn(carry, px[j]);
        int a = t * 16 + j;
        dstb[(size_t)(a + 1) * RPT + (r + 1)] = o;
    }

    if (rblk == 0) {
        for (int i = tid; i < 513; i += 512) {
            dstb[i] = 0.f;
            dstb[(size_t)i * RPT] = 0.f;
        }
    }
}

// ---------------- K3: per-detection vals; warp-0 epilogue -------------------
__global__ void __launch_bounds__(192) k_detect(
    const int* __restrict__ det_b, const int* __restrict__ det_c,
    const int* __restrict__ det_r, const int* __restrict__ det_a,
    const int* __restrict__ radus, const float* __restrict__ pred,
    float* __restrict__ out)
{
    const int g = blockIdx.x;
    const int t = threadIdx.x;

    __shared__ float v3[Kc][NS];

    if (t < Kc * NS) {
        const int k  = t / NS;
        const int s  = t % NS;
        const int sh = s - 20;
        const int gk = g * Kc + k;
        const int dr = det_r[gk], da = det_a[gk], db = det_b[gk];
        const int dc = det_c[gk], rad = radus[gk];

        const int rc = dr + sh;
        const int r1 = min(max(rc - rad, 0), Rc);
        const int r2 = min(max(rc + rad + 1, 0), Rc);
        const int a1 = min(max(da - 2, 0), Ac);
        const int a2 = min(max(da + 3, 0), Ac);

        const float w = g_w[s];

        const float* sc = g_satc + (size_t)(db * Cc + dc) * SST + BOFF;
        const float* sa = g_sata + (size_t)db * SST + BOFF;

        float c22 = __ldg(sc + (size_t)a2 * RPT + r2), c12 = __ldg(sc + (size_t)a2 * RPT + r1);
        float c21 = __ldg(sc + (size_t)a1 * RPT + r2), c11 = __ldg(sc + (size_t)a1 * RPT + r1);
        float rect4 = __fadd_rn(__fsub_rn(__fsub_rn(c22, c12), c21), c11);
        float val1  = __fmul_rn(rect4, w);

        float d22 = __ldg(sa + (size_t)a2 * RPT + r2), d12 = __ldg(sa + (size_t)a2 * RPT + r1);
        float d21 = __ldg(sa + (size_t)a1 * RPT + r2), d11 = __ldg(sa + (size_t)a1 * RPT + r1);
        float rect3 = __fadd_rn(__fsub_rn(__fsub_rn(d22, d12), d21), d11);
        float val2  = __fmul_rn(rect3, w);

        float val3 = __fadd_rn(__fmul_rn(0.5f, val1),
                               __fmul_rn(0.5f, __fsub_rn(val2, val1)));
        v3[k][s] = val3;
    }
    __syncthreads();

    if (t < 32) {   // warp 0 epilogue
        const int s1 = t;
        float bv;
        int   bi = s1;
        float se1 = __fadd_rn(__fadd_rn(__fadd_rn(v3[0][s1], v3[1][s1]), v3[2][s1]), v3[3][s1]);
        out[(size_t)g * NS + s1] = se1;
        bv = se1;
        const int s2 = t + 32;
        if (s2 < NS) {
            float se2 = __fadd_rn(__fadd_rn(__fadd_rn(v3[0][s2], v3[1][s2]), v3[2][s2]), v3[3][s2]);
            out[(size_t)g * NS + s2] = se2;
            if (se2 > bv) { bv = se2; bi = s2; }
        }
        #pragma unroll
        for (int off = 16; off > 0; off >>= 1) {
            float ov = __shfl_xor_sync(0xffffffffu, bv, off);
            int   oi = __shfl_xor_sync(0xffffffffu, bi, off);
            if (ov > bv || (ov == bv && oi < bi)) { bv = ov; bi = oi; }
        }
        const int shift = bi - 20;

        float pmv = 0.3f;
        if (t < 12) {
            const int kk = t / 3, cch = t % 3;
            const int gg = g * Kc + kk;
            const int rr = min(max(det_r[gg] + shift, 0), Rc - 1);
            const int db = det_b[gg], da = det_a[gg];
            pmv = fmaxf(pmv, __ldg(pred + (((size_t)db * Cc + cch) * Rc + rr) * Ac + da));
        }
        #pragma unroll
        for (int off = 16; off > 0; off >>= 1)
            pmv = fmaxf(pmv, __shfl_xor_sync(0xffffffffu, pmv, off));

        if (t == 0) {
            out[(size_t)Gc * NS       + g] = (float)shift;
            out[(size_t)Gc * (NS + 1) + g] = bv;
            out[(size_t)Gc * (NS + 2) + g] = pmv;
        }
    }
}

extern "C" void kernel_launch(void* const* d_in, const int* in_sizes, int n_in,
                              void* d_out, int out_size)
{
    const float* pred  = (const float*)d_in[0];
    const int*   det_b = (const int*)  d_in[1];
    const int*   det_c = (const int*)  d_in[2];
    const int*   det_r = (const int*)  d_in[3];
    const int*   det_a = (const int*)  d_in[4];
    const int*   radus = (const int*)  d_in[5];
    float*       out   = (float*)d_out;

    // one-time side stream + events (host objects only; no device memory)
    static cudaStream_t s2 = nullptr;
    static cudaEvent_t  evRoot = nullptr, evH[2] = {nullptr, nullptr};
    if (!s2) {
        cudaStreamCreateWithFlags(&s2, cudaStreamNonBlocking);
        cudaEventCreateWithFlags(&evRoot, cudaEventDisableTiming);
        for (int i = 0; i < 2; i++)
            cudaEventCreateWithFlags(&evH[i], cudaEventDisableTiming);
    }

    // fork side stream from the (possibly capturing) legacy stream
    cudaEventRecord(evRoot, 0);
    cudaStreamWaitEvent(s2, evRoot, 0);

    // K1 halves on s2; K2 half i on legacy stream after evH[i]
    for (int i = 0; i < 2; i++) {
        k_rowscan<<<(Bc / 2) * (Ac / 32), 1024, 0, s2>>>(pred, 8 * i);
        cudaEventRecord(evH[i], s2);
    }
    for (int i = 0; i < 2; i++) {
        cudaStreamWaitEvent(0, evH[i], 0);
        k_colscan<<<(Bc / 2) * Qc * 32, 512>>>(8 * i);
    }

    k_detect<<<Gc, 192>>>(det_b, det_c, det_r, det_a, radus, pred, out);
}